// round 9
// baseline (speedup 1.0000x reference)
#include <cuda_runtime.h>

#define NUM_CAT   16
#define NUM_ATTR  144
#define NUM_NUM   128
#define N_ARY     32
#define NUM_SEG   100000
#define N_ROWS    1000000

// Scratch (device globals — no allocation allowed in kernel_launch)
__device__ __align__(16) float g_agg[NUM_SEG * N_ARY];   // 12.8 MB, L2-resident
__device__ int   g_catidx[N_ROWS];                        // compact per-row segment id
__device__ float g_conf[N_ARY];                           // conf by OUTPUT rank
__device__ int   g_cols_sorted[N_ARY];                    // selected NUMERIC col (0..127), ascending
__device__ int   g_slot_of_rank[N_ARY];                   // rank k -> slot in sorted order
__device__ int   g_catcol;

#define ZERO_BLOCKS 391           // 391*256*8 = 800,768 float4 >= 800,000
#define ZERO_PER_T  8

// ---------------------------------------------------------------------------
// Kernel 0: fused init. Last block / warp 0: warp-parallel softmax + top-k.
// Blocks 0..390: zero agg, 8 float4 per thread (was 1 -> launch-latency bound).
// ---------------------------------------------------------------------------
__global__ void k_init(const float* __restrict__ cat_mask,
                       const float* __restrict__ num_mask) {
    const unsigned FULL = 0xffffffffu;

    if (blockIdx.x < ZERO_BLOCKS) {
        const int total = NUM_SEG * N_ARY / 4;            // 800,000 float4
        int base = (blockIdx.x * 256 + threadIdx.x) * ZERO_PER_T;
        float4 z = make_float4(0.f, 0.f, 0.f, 0.f);
#pragma unroll
        for (int j = 0; j < ZERO_PER_T; j++) {
            int i = base + j;
            if (i < total) reinterpret_cast<float4*>(g_agg)[i] = z;
        }
        return;
    }
    if (threadIdx.x >= 32) return;
    int lane = threadIdx.x;

    // --- categorical softmax + top-1 (16 values across lanes 0..15) ---
    float cv = (lane < NUM_CAT) ? cat_mask[lane] : -1e30f;
    float cm = cv;
    for (int o = 16; o; o >>= 1) cm = fmaxf(cm, __shfl_xor_sync(FULL, cm, o));
    float ce = (lane < NUM_CAT) ? expf(cv - cm) : 0.f;
    float cs = ce;
    for (int o = 16; o; o >>= 1) cs += __shfl_xor_sync(FULL, cs, o);
    float cp = ce / cs;
    float bv = cp; int bi = lane;
    for (int o = 16; o; o >>= 1) {               // argmax, first-index tie-break
        float ov = __shfl_xor_sync(FULL, bv, o);
        int   oi = __shfl_xor_sync(FULL, bi, o);
        if (ov > bv || (ov == bv && oi < bi)) { bv = ov; bi = oi; }
    }
    float top_cat_val = bv;
    if (lane == 0) g_catcol = bi;

    // --- numeric softmax (128 values: lane holds cols lane+32j) ---
    float nv[4];
#pragma unroll
    for (int j = 0; j < 4; j++) nv[j] = num_mask[lane + 32 * j];
    float nm = fmaxf(fmaxf(nv[0], nv[1]), fmaxf(nv[2], nv[3]));
    for (int o = 16; o; o >>= 1) nm = fmaxf(nm, __shfl_xor_sync(FULL, nm, o));
    float ns = 0.f;
#pragma unroll
    for (int j = 0; j < 4; j++) { nv[j] = expf(nv[j] - nm); ns += nv[j]; }
    for (int o = 16; o; o >>= 1) ns += __shfl_xor_sync(FULL, ns, o);
    float inv = 1.f / ns;
#pragma unroll
    for (int j = 0; j < 4; j++) nv[j] *= inv;    // probs > 0, so -1 marks "used"

    // --- top-32: 32 warp-argmax rounds; lane k keeps rank-k (col,val) ---
    int my_col = 0; float my_val = 0.f;
    for (int k = 0; k < N_ARY; k++) {
        float lb = nv[0]; int lj = 0;
#pragma unroll
        for (int j = 1; j < 4; j++) if (nv[j] > lb) { lb = nv[j]; lj = j; }
        float gv = lb; int gc = lane + 32 * lj;
        for (int o = 16; o; o >>= 1) {           // max val, smallest col on tie
            float ov = __shfl_xor_sync(FULL, gv, o);
            int   oc = __shfl_xor_sync(FULL, gc, o);
            if (ov > gv || (ov == gv && oc < gc)) { gv = ov; gc = oc; }
        }
        if (lane == k) { my_col = gc; my_val = gv; }
        if ((gc & 31) == lane) nv[gc >> 5] = -1.f;   // mark used at owner lane
    }

    g_conf[lane] = 0.5f * (my_val + top_cat_val);

    // rank of my_col among the 32 selected (ascending; cols are distinct)
    int rank = 0;
    for (int j = 0; j < N_ARY; j++) {
        int oc = __shfl_sync(FULL, my_col, j);
        rank += (oc < my_col);
    }
    g_cols_sorted[rank]  = my_col;               // numeric-relative (0..127)
    g_slot_of_rank[lane] = rank;
}

// ---------------------------------------------------------------------------
// Kernel 1: scatter-add. Warp handles 4 rows.
//   phase 1: front-batched __ldcs float4 loads (MLP=5 incl. idx; evict-first
//            so the 512MB input stream doesn't thrash the L2-resident agg)
//   phase 2: park rows in padded shared (132-float stride)
//   phase 3: 8 lanes/row pick 4 sorted columns from LDS, ONE
//            red.global.add.v4.f32 into agg (L2-hit).
// ---------------------------------------------------------------------------
__global__ void k_scatter(const float* __restrict__ inputs,
                          const int* __restrict__ idx_inputs) {
    __shared__ __align__(16) float s_row[8][4][132];   // 8 warps x 4 rows, +4 pad
    __shared__ int s_cols[N_ARY];
    __shared__ int s_catcol;
    if (threadIdx.x < N_ARY)  s_cols[threadIdx.x] = g_cols_sorted[threadIdx.x];
    if (threadIdx.x == N_ARY) s_catcol = g_catcol;
    __syncthreads();

    int warp = threadIdx.x >> 5;
    int lane = threadIdx.x & 31;
    int base = (blockIdx.x * 8 + warp) * 4;            // 4 rows per warp

    int j  = lane >> 3;                                // row within the 4-group
    int g  = lane & 7;                                 // slot-quad owner
    int r  = base + j;

    // ---- front-batch all global loads (idx + 4 row quarters) ----
    int seg = __ldg(&idx_inputs[(size_t)r * NUM_CAT + s_catcol]); // 8-lane bcast
    float4 v[4];
#pragma unroll
    for (int q = 0; q < 4; q++) {
        v[q] = __ldcs(reinterpret_cast<const float4*>(
                   inputs + (size_t)(base + q) * NUM_ATTR + NUM_CAT) + lane);
    }

#pragma unroll
    for (int q = 0; q < 4; q++)
        *reinterpret_cast<float4*>(&s_row[warp][q][lane * 4]) = v[q];
    __syncwarp();

    seg = min(max(seg, 0), NUM_SEG - 1);               // defensive: never OOB
    if (g == 0) g_catidx[r] = seg;                     // compact copy for gather

    const float* srow = s_row[warp][j];
    float v0 = srow[s_cols[4 * g + 0]];
    float v1 = srow[s_cols[4 * g + 1]];
    float v2 = srow[s_cols[4 * g + 2]];
    float v3 = srow[s_cols[4 * g + 3]];

    float* dst = &g_agg[(size_t)seg * N_ARY + 4 * g];  // 16B-aligned
    asm volatile("red.global.add.v4.f32 [%0], {%1,%2,%3,%4};"
                 :: "l"(dst), "f"(v0), "f"(v1), "f"(v2), "f"(v3)
                 : "memory");
}

// ---------------------------------------------------------------------------
// Kernel 2: gather + scale. 32 rows/warp (MLP=32; profiled latency-bound at
// issue 25%). out written with __stwt so the 128MB stream bypasses-to-memory
// and keeps agg L2-resident.
// ---------------------------------------------------------------------------
__global__ void k_gather(float* __restrict__ out) {
    __shared__ int   s_slot[N_ARY];
    __shared__ float s_conf[N_ARY];
    if (threadIdx.x < N_ARY) {
        s_slot[threadIdx.x] = g_slot_of_rank[threadIdx.x];
        s_conf[threadIdx.x] = g_conf[threadIdx.x];
    }
    __syncthreads();

    int warp = threadIdx.x >> 5;
    int lane = threadIdx.x & 31;
    int  slot = s_slot[lane];
    float conf = s_conf[lane];

    int base = (blockIdx.x * 8 + warp) * 32;           // 8 warps x 32 rows
    if (base >= N_ROWS) return;                        // tail warps (grid rounded up)

    int segs[32];
#pragma unroll
    for (int k = 0; k < 32; k++) segs[k] = g_catidx[base + k];  // batched (MLP)

#pragma unroll
    for (int k = 0; k < 32; k++) {
        float val = g_agg[(size_t)segs[k] * N_ARY + slot] * conf;
        __stwt(&out[(size_t)(base + k) * N_ARY + lane], val);
    }
}

// ---------------------------------------------------------------------------
extern "C" void kernel_launch(void* const* d_in, const int* in_sizes, int n_in,
                              void* d_out, int out_size) {
    const float* inputs     = (const float*)d_in[0];
    const int*   idx_inputs = (const int*)d_in[1];     // int32 (JAX x64 off)
    const float* cat_mask   = (const float*)d_in[2];
    const float* num_mask   = (const float*)d_in[3];
    float*       out        = (float*)d_out;

    k_init<<<ZERO_BLOCKS + 1, 256>>>(cat_mask, num_mask);
    k_scatter<<<31250, 256>>>(inputs, idx_inputs);      // 8 warps x 4 rows
    k_gather<<<3907, 256>>>(out);                       // 8 warps x 32 rows (tail-guarded)
}

// round 10
// speedup vs baseline: 1.0138x; 1.0138x over previous
#include <cuda_runtime.h>

#define NUM_CAT   16
#define NUM_ATTR  144
#define NUM_NUM   128
#define N_ARY     32
#define NUM_SEG   100000
#define N_ROWS    1000000

// Scratch (device globals — no allocation allowed in kernel_launch)
__device__ __align__(16) float g_agg[NUM_SEG * N_ARY];   // 12.8 MB, L2-resident
__device__ int   g_catidx[N_ROWS];                        // compact per-row segment id
__device__ float g_conf[N_ARY];                           // conf by OUTPUT rank
__device__ int   g_cols_sorted[N_ARY];                    // selected NUMERIC col (0..127), ascending
__device__ int   g_slot_of_rank[N_ARY];                   // rank k -> slot in sorted order
__device__ int   g_catcol;

// ---------------------------------------------------------------------------
// Kernel 0a: setup, 1 warp. Rank-based top-k: two all-pairs passes of
// INDEPENDENT shfl broadcasts (pipelined) instead of 32 dependent
// argmax-reduction rounds (~13k serial cycles -> ~2k pipelined).
// ---------------------------------------------------------------------------
__global__ void k_setup(const float* __restrict__ cat_mask,
                        const float* __restrict__ num_mask) {
    const unsigned FULL = 0xffffffffu;
    int lane = threadIdx.x;

    // --- categorical softmax + top-1 (16 values across lanes 0..15) ---
    float cv = (lane < NUM_CAT) ? cat_mask[lane] : -1e30f;
    float cm = cv;
    for (int o = 16; o; o >>= 1) cm = fmaxf(cm, __shfl_xor_sync(FULL, cm, o));
    float ce = (lane < NUM_CAT) ? expf(cv - cm) : 0.f;
    float cs = ce;
    for (int o = 16; o; o >>= 1) cs += __shfl_xor_sync(FULL, cs, o);
    float cp = ce / cs;
    float bv = cp; int bi = lane;
    for (int o = 16; o; o >>= 1) {               // argmax, first-index tie-break
        float ov = __shfl_xor_sync(FULL, bv, o);
        int   oi = __shfl_xor_sync(FULL, bi, o);
        if (ov > bv || (ov == bv && oi < bi)) { bv = ov; bi = oi; }
    }
    float top_cat_val = bv;
    if (lane == 0) g_catcol = bi;

    // --- numeric softmax (lane holds cols lane, lane+32, lane+64, lane+96) ---
    float nv[4];
#pragma unroll
    for (int j = 0; j < 4; j++) nv[j] = num_mask[lane + 32 * j];
    float nm = fmaxf(fmaxf(nv[0], nv[1]), fmaxf(nv[2], nv[3]));
    for (int o = 16; o; o >>= 1) nm = fmaxf(nm, __shfl_xor_sync(FULL, nm, o));
    float ns = 0.f;
#pragma unroll
    for (int j = 0; j < 4; j++) { nv[j] = expf(nv[j] - nm); ns += nv[j]; }
    for (int o = 16; o; o >>= 1) ns += __shfl_xor_sync(FULL, ns, o);
    float inv = 1.f / ns;
#pragma unroll
    for (int j = 0; j < 4; j++) nv[j] *= inv;

    // --- pass 1: descending rank of each value (stable: smaller col wins tie)
    int rk[4] = {0, 0, 0, 0};
    for (int s = 0; s < 32; s++) {
#pragma unroll
        for (int j2 = 0; j2 < 4; j2++) {
            float ov = __shfl_sync(FULL, nv[j2], s);
            int   oc = s + 32 * j2;
#pragma unroll
            for (int j = 0; j < 4; j++) {
                int mc = lane + 32 * j;
                rk[j] += (ov > nv[j]) || (ov == nv[j] && oc < mc);
            }
        }
    }

    // --- pass 2: ascending-column slot among the selected (rank < 32) ---
    int sl[4] = {0, 0, 0, 0};
    for (int s = 0; s < 32; s++) {
#pragma unroll
        for (int j2 = 0; j2 < 4; j2++) {
            int orank = __shfl_sync(FULL, rk[j2], s);
            int oc    = s + 32 * j2;
#pragma unroll
            for (int j = 0; j < 4; j++) {
                int mc = lane + 32 * j;
                sl[j] += (orank < N_ARY) && (oc < mc);
            }
        }
    }

#pragma unroll
    for (int j = 0; j < 4; j++) {
        if (rk[j] < N_ARY) {                      // this value is output rank rk[j]
            g_conf[rk[j]]         = 0.5f * (nv[j] + top_cat_val);
            g_cols_sorted[sl[j]]  = lane + 32 * j;   // numeric-relative col
            g_slot_of_rank[rk[j]] = sl[j];
        }
    }
}

// ---------------------------------------------------------------------------
// Kernel 0b: zero agg. Coalesced (j*blockDim stride -> warp stores stay
// 512B-contiguous), 4 float4/thread, runs every replay.
// ---------------------------------------------------------------------------
__global__ void k_zero() {
    const int total = NUM_SEG * N_ARY / 4;            // 800,000 float4
    int base = blockIdx.x * (256 * 4) + threadIdx.x;
    float4 z = make_float4(0.f, 0.f, 0.f, 0.f);
#pragma unroll
    for (int j = 0; j < 4; j++) {
        int i = base + j * 256;
        if (i < total) reinterpret_cast<float4*>(g_agg)[i] = z;
    }
}

// ---------------------------------------------------------------------------
// Kernel 1: scatter-add. Warp handles 4 rows.
//   front-batched __ldcs float4 loads (evict-first keeps agg L2-resident)
//   -> padded shared (132-float stride) -> 8 lanes/row pick 4 sorted columns
//   -> ONE red.global.add.v4.f32 per lane into the L2-resident agg table.
// ---------------------------------------------------------------------------
__global__ void k_scatter(const float* __restrict__ inputs,
                          const int* __restrict__ idx_inputs) {
    __shared__ __align__(16) float s_row[8][4][132];   // 8 warps x 4 rows, +4 pad
    __shared__ int s_cols[N_ARY];
    __shared__ int s_catcol;
    if (threadIdx.x < N_ARY)  s_cols[threadIdx.x] = g_cols_sorted[threadIdx.x];
    if (threadIdx.x == N_ARY) s_catcol = g_catcol;
    __syncthreads();

    int warp = threadIdx.x >> 5;
    int lane = threadIdx.x & 31;
    int base = (blockIdx.x * 8 + warp) * 4;            // 4 rows per warp

    int j = lane >> 3;                                 // row within the 4-group
    int g = lane & 7;                                  // slot-quad owner
    int r = base + j;

    // ---- front-batch all global loads (idx + 4 row quarters) ----
    int seg = __ldg(&idx_inputs[(size_t)r * NUM_CAT + s_catcol]); // 8-lane bcast
    float4 v[4];
#pragma unroll
    for (int q = 0; q < 4; q++) {
        v[q] = __ldcs(reinterpret_cast<const float4*>(
                   inputs + (size_t)(base + q) * NUM_ATTR + NUM_CAT) + lane);
    }

#pragma unroll
    for (int q = 0; q < 4; q++)
        *reinterpret_cast<float4*>(&s_row[warp][q][lane * 4]) = v[q];
    __syncwarp();

    seg = min(max(seg, 0), NUM_SEG - 1);               // defensive: never OOB
    if (g == 0) g_catidx[r] = seg;                     // compact copy for gather

    const float* srow = s_row[warp][j];
    float v0 = srow[s_cols[4 * g + 0]];
    float v1 = srow[s_cols[4 * g + 1]];
    float v2 = srow[s_cols[4 * g + 2]];
    float v3 = srow[s_cols[4 * g + 3]];

    float* dst = &g_agg[(size_t)seg * N_ARY + 4 * g];  // 16B-aligned
    asm volatile("red.global.add.v4.f32 [%0], {%1,%2,%3,%4};"
                 :: "l"(dst), "f"(v0), "f"(v1), "f"(v2), "f"(v3)
                 : "memory");
}

// ---------------------------------------------------------------------------
// Kernel 2: gather + scale. 32 rows/warp (MLP), __stwt output stream so the
// 128MB write doesn't evict the L2-resident agg.
// ---------------------------------------------------------------------------
__global__ void k_gather(float* __restrict__ out) {
    __shared__ int   s_slot[N_ARY];
    __shared__ float s_conf[N_ARY];
    if (threadIdx.x < N_ARY) {
        s_slot[threadIdx.x] = g_slot_of_rank[threadIdx.x];
        s_conf[threadIdx.x] = g_conf[threadIdx.x];
    }
    __syncthreads();

    int warp = threadIdx.x >> 5;
    int lane = threadIdx.x & 31;
    int  slot = s_slot[lane];
    float conf = s_conf[lane];

    int base = (blockIdx.x * 8 + warp) * 32;           // 8 warps x 32 rows
    if (base >= N_ROWS) return;                        // tail warps

    int segs[32];
#pragma unroll
    for (int k = 0; k < 32; k++) segs[k] = g_catidx[base + k];  // batched (MLP)

#pragma unroll
    for (int k = 0; k < 32; k++) {
        float val = g_agg[(size_t)segs[k] * N_ARY + slot] * conf;
        __stwt(&out[(size_t)(base + k) * N_ARY + lane], val);
    }
}

// ---------------------------------------------------------------------------
extern "C" void kernel_launch(void* const* d_in, const int* in_sizes, int n_in,
                              void* d_out, int out_size) {
    const float* inputs     = (const float*)d_in[0];
    const int*   idx_inputs = (const int*)d_in[1];     // int32 (JAX x64 off)
    const float* cat_mask   = (const float*)d_in[2];
    const float* num_mask   = (const float*)d_in[3];
    float*       out        = (float*)d_out;

    k_setup<<<1, 32>>>(cat_mask, num_mask);             // ~1.5us, pipelined ranks
    k_zero<<<782, 256>>>();                             // coalesced, 4 f4/thread
    k_scatter<<<31250, 256>>>(inputs, idx_inputs);      // 8 warps x 4 rows
    k_gather<<<3907, 256>>>(out);                       // 8 warps x 32 rows
}

// round 13
// speedup vs baseline: 1.2044x; 1.1880x over previous
#include <cuda_runtime.h>

#define NUM_CAT   16
#define NUM_ATTR  144
#define NUM_NUM   128
#define N_ARY     32
#define NUM_SEG   100000
#define N_ROWS    1000000

// Scratch (device globals — no allocation allowed in kernel_launch)
__device__ __align__(16) float g_agg[NUM_SEG * N_ARY];   // 12.8 MB, L2-resident; slot = output rank
__device__ int   g_catidx[N_ROWS];                        // compact per-row segment id
__device__ __align__(16) float g_conf[N_ARY];             // conf by output rank
__device__ int   g_cols_rank[N_ARY];                      // rank k -> numeric col (0..127)
__device__ int   g_catcol;

// ---------------------------------------------------------------------------
// Kernel 0a: setup, 1 warp. Rank-based top-k: ONE all-pairs pass of
// independent shfl broadcasts (pipelined). Rank == agg slot == output column,
// so no sort / slot permutation needed anywhere.
// ---------------------------------------------------------------------------
__global__ void k_setup(const float* __restrict__ cat_mask,
                        const float* __restrict__ num_mask) {
    const unsigned FULL = 0xffffffffu;
    int lane = threadIdx.x;

    // --- categorical softmax + top-1 (16 values across lanes 0..15) ---
    float cv = (lane < NUM_CAT) ? cat_mask[lane] : -1e30f;
    float cm = cv;
    for (int o = 16; o; o >>= 1) cm = fmaxf(cm, __shfl_xor_sync(FULL, cm, o));
    float ce = (lane < NUM_CAT) ? expf(cv - cm) : 0.f;
    float cs = ce;
    for (int o = 16; o; o >>= 1) cs += __shfl_xor_sync(FULL, cs, o);
    float cp = ce / cs;
    float bv = cp; int bi = lane;
    for (int o = 16; o; o >>= 1) {               // argmax, first-index tie-break
        float ov = __shfl_xor_sync(FULL, bv, o);
        int   oi = __shfl_xor_sync(FULL, bi, o);
        if (ov > bv || (ov == bv && oi < bi)) { bv = ov; bi = oi; }
    }
    float top_cat_val = bv;
    if (lane == 0) g_catcol = bi;

    // --- numeric softmax (lane holds cols lane, lane+32, lane+64, lane+96) ---
    float nv[4];
#pragma unroll
    for (int j = 0; j < 4; j++) nv[j] = num_mask[lane + 32 * j];
    float nm = fmaxf(fmaxf(nv[0], nv[1]), fmaxf(nv[2], nv[3]));
    for (int o = 16; o; o >>= 1) nm = fmaxf(nm, __shfl_xor_sync(FULL, nm, o));
    float ns = 0.f;
#pragma unroll
    for (int j = 0; j < 4; j++) { nv[j] = expf(nv[j] - nm); ns += nv[j]; }
    for (int o = 16; o; o >>= 1) ns += __shfl_xor_sync(FULL, ns, o);
    float inv = 1.f / ns;
#pragma unroll
    for (int j = 0; j < 4; j++) nv[j] *= inv;

    // --- descending rank of each value (stable: smaller col wins tie) ---
    int rk[4] = {0, 0, 0, 0};
    for (int s = 0; s < 32; s++) {
#pragma unroll
        for (int j2 = 0; j2 < 4; j2++) {
            float ov = __shfl_sync(FULL, nv[j2], s);
            int   oc = s + 32 * j2;
#pragma unroll
            for (int j = 0; j < 4; j++) {
                int mc = lane + 32 * j;
                rk[j] += (ov > nv[j]) || (ov == nv[j] && oc < mc);
            }
        }
    }

#pragma unroll
    for (int j = 0; j < 4; j++) {
        if (rk[j] < N_ARY) {                      // this value is output rank rk[j]
            g_conf[rk[j]]      = 0.5f * (nv[j] + top_cat_val);
            g_cols_rank[rk[j]] = lane + 32 * j;   // numeric-relative col
        }
    }
}

// ---------------------------------------------------------------------------
// Kernel 0b: zero agg. Coalesced (j*blockDim stride), 4 float4/thread.
// ---------------------------------------------------------------------------
__global__ void k_zero() {
    const int total = NUM_SEG * N_ARY / 4;            // 800,000 float4
    int base = blockIdx.x * (256 * 4) + threadIdx.x;
    float4 z = make_float4(0.f, 0.f, 0.f, 0.f);
#pragma unroll
    for (int j = 0; j < 4; j++) {
        int i = base + j * 256;
        if (i < total) reinterpret_cast<float4*>(g_agg)[i] = z;
    }
}

// ---------------------------------------------------------------------------
// Kernel 1: scatter-add. Warp handles 4 rows.
//   front-batched __ldcs float4 loads (evict-first keeps agg L2-resident)
//   -> padded shared (132-float stride) -> 8 lanes/row pick ranks 4g..4g+3
//   -> ONE red.global.add.v4.f32 per lane into the L2-resident agg table.
// ---------------------------------------------------------------------------
__global__ void k_scatter(const float* __restrict__ inputs,
                          const int* __restrict__ idx_inputs) {
    __shared__ __align__(16) float s_row[8][4][132];   // 8 warps x 4 rows, +4 pad
    __shared__ int s_cols[N_ARY];
    __shared__ int s_catcol;
    if (threadIdx.x < N_ARY)  s_cols[threadIdx.x] = g_cols_rank[threadIdx.x];
    if (threadIdx.x == N_ARY) s_catcol = g_catcol;
    __syncthreads();

    int warp = threadIdx.x >> 5;
    int lane = threadIdx.x & 31;
    int base = (blockIdx.x * 8 + warp) * 4;            // 4 rows per warp

    int j = lane >> 3;                                 // row within the 4-group
    int g = lane & 7;                                  // rank-quad owner
    int r = base + j;

    // ---- front-batch all global loads (idx + 4 row quarters) ----
    int seg = __ldg(&idx_inputs[(size_t)r * NUM_CAT + s_catcol]); // 8-lane bcast
    float4 v[4];
#pragma unroll
    for (int q = 0; q < 4; q++) {
        v[q] = __ldcs(reinterpret_cast<const float4*>(
                   inputs + (size_t)(base + q) * NUM_ATTR + NUM_CAT) + lane);
    }

#pragma unroll
    for (int q = 0; q < 4; q++)
        *reinterpret_cast<float4*>(&s_row[warp][q][lane * 4]) = v[q];
    __syncwarp();

    seg = min(max(seg, 0), NUM_SEG - 1);               // defensive: never OOB
    if (g == 0) g_catidx[r] = seg;                     // compact copy for gather

    const float* srow = s_row[warp][j];
    float v0 = srow[s_cols[4 * g + 0]];
    float v1 = srow[s_cols[4 * g + 1]];
    float v2 = srow[s_cols[4 * g + 2]];
    float v3 = srow[s_cols[4 * g + 3]];

    float* dst = &g_agg[(size_t)seg * N_ARY + 4 * g];  // 16B-aligned, slot=rank
    asm volatile("red.global.add.v4.f32 [%0], {%1,%2,%3,%4};"
                 :: "l"(dst), "f"(v0), "f"(v1), "f"(v2), "f"(v3)
                 : "memory");
}

// ---------------------------------------------------------------------------
// Kernel 2: gather + scale, float4 path (agg slot == output rank, so the row
// copy is a straight vector op). 8 lanes x float4 per row, 4 rows per warp
// per step, 4 front-batched steps = 16 rows/warp. 1 LDG.128 + 1 STG.128 per
// row instead of 32 scalar LDG+STG (R10 profile: issue-bound, regs 48).
// ---------------------------------------------------------------------------
__global__ void k_gather(float* __restrict__ out) {
    __shared__ float4 s_conf4[8];
    if (threadIdx.x < 8)
        s_conf4[threadIdx.x] = reinterpret_cast<const float4*>(g_conf)[threadIdx.x];
    __syncthreads();

    int warp = threadIdx.x >> 5;
    int lane = threadIdx.x & 31;
    int q  = lane & 7;                                 // float4 index within row
    int jr = lane >> 3;                                // row within step-quad
    float4 conf4 = s_conf4[q];

    int base = (blockIdx.x * 8 + warp) * 16;           // 16 rows per warp
    if (base >= N_ROWS) return;                        // tail warps (exact: 62500 warps)

    int segs[4];
#pragma unroll
    for (int s = 0; s < 4; s++)
        segs[s] = g_catidx[base + s * 4 + jr];         // 8-lane broadcast loads

    float4 v[4];
#pragma unroll
    for (int s = 0; s < 4; s++)
        v[s] = reinterpret_cast<const float4*>(g_agg)[(size_t)segs[s] * 8 + q];

#pragma unroll
    for (int s = 0; s < 4; s++) {
        int r = base + s * 4 + jr;
        float4 o = make_float4(v[s].x * conf4.x, v[s].y * conf4.y,
                               v[s].z * conf4.z, v[s].w * conf4.w);
        reinterpret_cast<float4*>(out)[(size_t)r * 8 + q] = o;
    }
}

// ---------------------------------------------------------------------------
extern "C" void kernel_launch(void* const* d_in, const int* in_sizes, int n_in,
                              void* d_out, int out_size) {
    const float* inputs     = (const float*)d_in[0];
    const int*   idx_inputs = (const int*)d_in[1];     // int32 (JAX x64 off)
    const float* cat_mask   = (const float*)d_in[2];
    const float* num_mask   = (const float*)d_in[3];
    float*       out        = (float*)d_out;

    k_setup<<<1, 32>>>(cat_mask, num_mask);
    k_zero<<<782, 256>>>();
    k_scatter<<<31250, 256>>>(inputs, idx_inputs);      // 8 warps x 4 rows
    k_gather<<<7813, 256>>>(out);                       // 8 warps x 16 rows, float4
}